// round 15
// baseline (speedup 1.0000x reference)
#include <cuda_runtime.h>

// Problem constants
#define NG 4        // bands (G)
#define NB 128      // batch (B)
#define NNODE 30    // nodes (N)
#define NF 5000     // features (F)
#define NC 10       // out channels (C)
#define ROWS_G (NB*NNODE)   // 3840 rows per (mod,g)

// ---------------- device scratch (no allocations allowed) ----------------
__device__ float g_h[3 * NG * ROWS_G * NC];      // h for eeg/emg/cmc
__device__ float g_Wt[12 * NC * NF];             // W transposed: [(mod*4+g)*10+c][k]
__device__ float g_cor[NG * NNODE * NNODE];      // mean over T of cmc_train

typedef unsigned long long ull;

// ---------------- f32x2 packed helpers (sm_103a) ----------------
__device__ __forceinline__ ull pack2(float a, float b) {
    ull r;
    unsigned x = __float_as_uint(a), y = __float_as_uint(b);
    asm("mov.b64 %0, {%1, %2};" : "=l"(r) : "r"(x), "r"(y));
    return r;
}
__device__ __forceinline__ ull dup2(float a) {
    ull r;
    unsigned x = __float_as_uint(a);
    asm("mov.b64 %0, {%1, %1};" : "=l"(r) : "r"(x));
    return r;
}
__device__ __forceinline__ void unpack2(ull v, float& lo, float& hi) {
    unsigned x, y;
    asm("mov.b64 {%0, %1}, %2;" : "=r"(x), "=r"(y) : "l"(v));
    lo = __uint_as_float(x); hi = __uint_as_float(y);
}
__device__ __forceinline__ void ffma2(ull& d, ull a, ull b) {
    asm("fma.rn.f32x2 %0, %1, %2, %0;" : "+l"(d) : "l"(a), "l"(b));
}
__device__ __forceinline__ ull add2(ull a, ull b) {
    ull d;
    asm("add.rn.f32x2 %0, %1, %2;" : "=l"(d) : "l"(a), "l"(b));
    return d;
}
__device__ __forceinline__ float warp_max(float v) {
#pragma unroll
    for (int off = 16; off > 0; off >>= 1)
        v = fmaxf(v, __shfl_xor_sync(0xffffffffu, v, off));
    return v;
}
__device__ __forceinline__ float warp_sum(float v) {
#pragma unroll
    for (int off = 16; off > 0; off >>= 1)
        v += __shfl_xor_sync(0xffffffffu, v, off);
    return v;
}

// =====================================================================
// Kernel 0: prep — finer grain than R14 (latency-bound; more blocks =
// shorter dependent chains). Blocks 0..599: transpose a 100-k chunk
// (12 mg x 50). Blocks 600..603: cor = mean_t cmc_train (per g).
// =====================================================================
#define KCH 100

__global__ __launch_bounds__(256) void k0_prep(
    const float* __restrict__ Weeg, const float* __restrict__ Wemg,
    const float* __restrict__ Wcmc, const float* __restrict__ cmc_train)
{
    __shared__ float sbuf[KCH * NC];   // 1000 floats
    int blk = blockIdx.x, tid = threadIdx.x;
    if (blk < 600) {
        int mg = blk / 50, chunk = blk % 50;
        int kbase = chunk * KCH;
        int mod = mg >> 2, g = mg & 3;
        const float* Wsrc = ((mod == 0) ? Weeg : ((mod == 1) ? Wemg : Wcmc))
                            + (size_t)g * NF * NC + (size_t)kbase * NC;
        for (int i = tid; i < KCH * NC; i += 256) sbuf[i] = Wsrc[i];
        __syncthreads();
        for (int t = tid; t < KCH * NC; t += 256) {
            int c = t / KCH, k = t % KCH;
            g_Wt[((size_t)mg * NC + c) * NF + kbase + k] = sbuf[k * NC + c];
        }
    } else {
        int g = blk - 600;
        for (int i = tid; i < NNODE * NNODE; i += 256) {
            float s = 0.f;
#pragma unroll
            for (int t = 0; t < 8; t++)
                s += cmc_train[(size_t)t * (NG * NNODE * NNODE)
                               + (size_t)g * (NNODE * NNODE) + i];
            g_cor[g * NNODE * NNODE + i] = s * 0.125f;
        }
    }
}

// =====================================================================
// Kernel 1: (byte-identical to R12/R13/R14 passing version; k1 is at
// its empirical DRAM-shape ceiling ~4.9TB/s, all redesigns falsified)
// =====================================================================
#define STEP256(BUF, KB, DOREF, RKB)                                        \
    {                                                                       \
        ull p01_0x = pack2(BUF[0][0].x, BUF[1][0].x);                       \
        ull p01_0y = pack2(BUF[0][0].y, BUF[1][0].y);                       \
        ull p01_0z = pack2(BUF[0][0].z, BUF[1][0].z);                       \
        ull p01_0w = pack2(BUF[0][0].w, BUF[1][0].w);                       \
        ull p23_0x = pack2(BUF[2][0].x, BUF[3][0].x);                       \
        ull p23_0y = pack2(BUF[2][0].y, BUF[3][0].y);                       \
        ull p23_0z = pack2(BUF[2][0].z, BUF[3][0].z);                       \
        ull p23_0w = pack2(BUF[2][0].w, BUF[3][0].w);                       \
        ull p01_1x = pack2(BUF[0][1].x, BUF[1][1].x);                       \
        ull p01_1y = pack2(BUF[0][1].y, BUF[1][1].y);                       \
        ull p01_1z = pack2(BUF[0][1].z, BUF[1][1].z);                       \
        ull p01_1w = pack2(BUF[0][1].w, BUF[1][1].w);                       \
        ull p23_1x = pack2(BUF[2][1].x, BUF[3][1].x);                       \
        ull p23_1y = pack2(BUF[2][1].y, BUF[3][1].y);                       \
        ull p23_1z = pack2(BUF[2][1].z, BUF[3][1].z);                       \
        ull p23_1w = pack2(BUF[2][1].w, BUF[3][1].w);                       \
        if (DOREF) {                                                        \
            _Pragma("unroll")                                               \
            for (int r = 0; r < 4; r++) {                                   \
                BUF[r][0] = __ldcs((const float4*)(p + r * NF + (RKB) + kl));\
                BUF[r][1] = __ldcs((const float4*)(p + r * NF + (RKB) + 128 + kl));\
            }                                                               \
        }                                                                   \
        _Pragma("unroll")                                                   \
        for (int c = 0; c < NC; c++) {                                      \
            float4 w0 = __ldg((const float4*)(wp + (size_t)c * NF + (KB)));  \
            float4 w1 = __ldg((const float4*)(wp + (size_t)c * NF + (KB) + 128));\
            ull wx = dup2(w0.x), wy = dup2(w0.y), wz = dup2(w0.z), ww = dup2(w0.w);\
            ffma2(a01[c], p01_0x, wx); ffma2(a01[c], p01_0y, wy);           \
            ffma2(a01[c], p01_0z, wz); ffma2(a01[c], p01_0w, ww);           \
            ffma2(a23[c], p23_0x, wx); ffma2(a23[c], p23_0y, wy);           \
            ffma2(a23[c], p23_0z, wz); ffma2(a23[c], p23_0w, ww);           \
            wx = dup2(w1.x); wy = dup2(w1.y); wz = dup2(w1.z); ww = dup2(w1.w);\
            ffma2(a01[c], p01_1x, wx); ffma2(a01[c], p01_1y, wy);           \
            ffma2(a01[c], p01_1z, wz); ffma2(a01[c], p01_1w, ww);           \
            ffma2(a23[c], p23_1x, wx); ffma2(a23[c], p23_1y, wy);           \
            ffma2(a23[c], p23_1z, wz); ffma2(a23[c], p23_1w, ww);           \
        }                                                                   \
    }

__global__ __launch_bounds__(128, 3) void k1_gemm(
    const float* __restrict__ eeg, const float* __restrict__ emg,
    const float* __restrict__ cmc)
{
    int blk = blockIdx.x;
    int mod = blk / 960;
    int rem = blk % 960;
    int g   = rem / 240;
    int r0  = (rem % 240) * 16;

    const float* x = (mod == 0) ? eeg : ((mod == 1) ? emg : cmc);

    int tid  = threadIdx.x;
    int lane = tid & 31;
    int wid  = tid >> 5;
    int kl   = lane * 4;

    int r0w = r0 + wid * 4;
    const float* p  = x + ((size_t)g * ROWS_G + r0w) * NF;
    const float* wp = g_Wt + (size_t)(mod * NG + g) * (NC * NF) + kl;

    ull a01[NC], a23[NC];
#pragma unroll
    for (int c = 0; c < NC; c++) { a01[c] = 0ull; a23[c] = 0ull; }

    float4 A[4][2], B[4][2];
#pragma unroll
    for (int r = 0; r < 4; r++) {
        A[r][0] = __ldcs((const float4*)(p + r * NF + 0   + kl));
        A[r][1] = __ldcs((const float4*)(p + r * NF + 128 + kl));
    }
#pragma unroll
    for (int r = 0; r < 4; r++) {
        B[r][0] = __ldcs((const float4*)(p + r * NF + 256 + kl));
        B[r][1] = __ldcs((const float4*)(p + r * NF + 384 + kl));
    }

#pragma unroll 1
    for (int s2 = 0; s2 < 9; ++s2) {
        int kb = s2 * 512;
        STEP256(A, kb, true, kb + 512)
        STEP256(B, kb + 256, (s2 < 8), kb + 768)
    }
    STEP256(A, 4608, false, 0)

    {
        float4 t0 = __ldcs((const float4*)(p + 0 * NF + 4864 + kl));
        float4 t1 = __ldcs((const float4*)(p + 1 * NF + 4864 + kl));
        float4 t2 = __ldcs((const float4*)(p + 2 * NF + 4864 + kl));
        float4 t3 = __ldcs((const float4*)(p + 3 * NF + 4864 + kl));
        ull x01x = pack2(t0.x, t1.x), x01y = pack2(t0.y, t1.y);
        ull x01z = pack2(t0.z, t1.z), x01w = pack2(t0.w, t1.w);
        ull x23x = pack2(t2.x, t3.x), x23y = pack2(t2.y, t3.y);
        ull x23z = pack2(t2.z, t3.z), x23w = pack2(t2.w, t3.w);
#pragma unroll
        for (int c = 0; c < NC; c++) {
            float4 w = __ldg((const float4*)(wp + (size_t)c * NF + 4864));
            ull wx = dup2(w.x), wy = dup2(w.y), wz = dup2(w.z), ww = dup2(w.w);
            ffma2(a01[c], x01x, wx); ffma2(a01[c], x01y, wy);
            ffma2(a01[c], x01z, wz); ffma2(a01[c], x01w, ww);
            ffma2(a23[c], x23x, wx); ffma2(a23[c], x23y, wy);
            ffma2(a23[c], x23z, wz); ffma2(a23[c], x23w, ww);
        }
    }

    if (lane < 2) {
        int ks = 4992 + kl;
        float4 x0 = __ldcs((const float4*)(p + 0 * NF + ks));
        float4 x1 = __ldcs((const float4*)(p + 1 * NF + ks));
        float4 x2 = __ldcs((const float4*)(p + 2 * NF + ks));
        float4 x3 = __ldcs((const float4*)(p + 3 * NF + ks));
        ull x01x = pack2(x0.x, x1.x), x01y = pack2(x0.y, x1.y);
        ull x01z = pack2(x0.z, x1.z), x01w = pack2(x0.w, x1.w);
        ull x23x = pack2(x2.x, x3.x), x23y = pack2(x2.y, x3.y);
        ull x23z = pack2(x2.z, x3.z), x23w = pack2(x2.w, x3.w);
#pragma unroll
        for (int c = 0; c < NC; c++) {
            float4 w = __ldg((const float4*)(wp + (size_t)c * NF + 4992));
            ull wx = dup2(w.x), wy = dup2(w.y), wz = dup2(w.z), ww = dup2(w.w);
            ffma2(a01[c], x01x, wx); ffma2(a01[c], x01y, wy);
            ffma2(a01[c], x01z, wz); ffma2(a01[c], x01w, ww);
            ffma2(a23[c], x23x, wx); ffma2(a23[c], x23y, wy);
            ffma2(a23[c], x23z, wz); ffma2(a23[c], x23w, ww);
        }
    }

    size_t outbase = ((size_t)(mod * NG + g) * ROWS_G + r0w) * NC;
#pragma unroll
    for (int c = 0; c < NC; c++) {
        ull v = a01[c];
#pragma unroll
        for (int off = 16; off > 0; off >>= 1)
            v = add2(v, __shfl_down_sync(0xffffffffu, v, off));
        if (lane == 0) {
            float lo, hi; unpack2(v, lo, hi);
            g_h[outbase + c]      = lo;
            g_h[outbase + NC + c] = hi;
        }
        v = a23[c];
#pragma unroll
        for (int off = 16; off > 0; off >>= 1)
            v = add2(v, __shfl_down_sync(0xffffffffu, v, off));
        if (lane == 0) {
            float lo, hi; unpack2(v, lo, hi);
            g_h[outbase + 2 * NC + c] = lo;
            g_h[outbase + 3 * NC + c] = hi;
        }
    }
}

// =====================================================================
// Kernel 2+3 FUSED: (byte-identical to R13/R14 passing version)
// =====================================================================
#define OFF_HX   0
#define OFF_FE   1200
#define OFF_FM   2400
#define OFF_FC   3600
#define OFF_ATT  4800
#define OFF_COR  8640
#define OFF_ADJ  12240
#define OFF_F1   15840
#define OFF_F2   15960
#define OFF_HG   16080
#define OFF_BAND 23760
#define OFF_GS   24960
#define OFF_POOL 25080
#define OFF_FEAT 25320
#define OFF_H1   25360
#define OFF_P1   25616
#define OFF_H2   25872
#define SM23_FLOATS 25904

#define GB() asm volatile("bar.sync %0, 128;" :: "r"(g + 1) : "memory")

__global__ __launch_bounds__(512, 1) void k23_fused(
    const float* __restrict__ wpli_eeg, const float* __restrict__ wpli_emg,
    const float* __restrict__ a_eeg, const float* __restrict__ a_emg,
    const float* __restrict__ b_cmc,
    const float* __restrict__ g0w1, const float* __restrict__ g0b1,
    const float* __restrict__ g0w2, const float* __restrict__ g0b2,
    const float* __restrict__ g1w1, const float* __restrict__ g1b1,
    const float* __restrict__ g1w2, const float* __restrict__ g1b2,
    const float* __restrict__ mlp0w, const float* __restrict__ mlp0b,
    const float* __restrict__ mlp1w, const float* __restrict__ mlp1b,
    const float* __restrict__ mlp2w, const float* __restrict__ mlp2b,
    const float* __restrict__ bng, const float* __restrict__ bnb,
    float* __restrict__ out)
{
    extern __shared__ float sm[];
    int b    = blockIdx.x;
    int tid  = threadIdx.x;
    int g    = tid >> 7;            // band group 0..3
    int lt   = tid & 127;
    int lane = tid & 31;
    int wg   = lt >> 5;             // warp within group 0..3

    float* hX   = sm + OFF_HX  + g * 300;     // [30][10]
    float* fE   = sm + OFF_FE  + g * 300;
    float* fM   = sm + OFF_FM  + g * 300;
    float* fC   = sm + OFF_FC  + g * 300;
    float* att  = sm + OFF_ATT + g * 960;     // [30][32]
    float* corS = sm + OFF_COR + g * 900;
    float* adjS = sm + OFF_ADJ + g * 900;
    float* f1s  = sm + OFF_F1  + g * 30;
    float* f2s  = sm + OFF_F2  + g * 30;
    float* hg   = sm + OFF_HG  + g * 1920;    // [30][64]
    float* band = sm + OFF_BAND;              // [30][40] shared by all

    // ================= k2 phase (per-group, named barriers) =============
    for (int i = lt; i < NNODE * NNODE; i += 128)
        corS[i] = g_cor[g * NNODE * NNODE + i];
    {
        size_t hb = ((size_t)(2 * NG + g) * ROWS_G + (size_t)b * NNODE) * NC;
        for (int i = lt; i < NNODE * NC; i += 128)
            hX[i] = g_h[hb + i];
    }
    GB();
    for (int idx = lt; idx < NNODE * NC; idx += 128) {
        int i = idx / NC, c = idx % NC;
        float s = 0.f;
        for (int j = 0; j < NNODE; j++) s += corS[i * NNODE + j] * hX[j * NC + c];
        fC[i * NC + c] = s + b_cmc[g * NC + c];
    }
    GB();

    for (int m = 0; m < 2; ++m) {
        const float* a   = ((m == 0) ? a_eeg : a_emg) + g * 2 * NC;
        const float* adj = ((m == 0) ? wpli_eeg : wpli_emg) + g * NNODE * NNODE;
        size_t hb = ((size_t)(m * NG + g) * ROWS_G + (size_t)b * NNODE) * NC;
        for (int i = lt; i < NNODE * NC; i += 128)
            hX[i] = g_h[hb + i];
        for (int i = lt; i < NNODE * NNODE; i += 128)
            adjS[i] = adj[i];
        GB();
        if (lt < NNODE) {
            float s1 = 0.f, s2 = 0.f;
#pragma unroll
            for (int c = 0; c < NC; c++) {
                s1 += hX[lt * NC + c] * a[c];
                s2 += hX[lt * NC + c] * a[NC + c];
            }
            f1s[lt] = s1; f2s[lt] = s2;
        }
        GB();
        {
            int i = lane;
#pragma unroll 1
            for (int jj = 0; jj < 8; ++jj) {
                int j = wg + 4 * jj;
                if (j >= NNODE) break;
                float v = -1e30f;
                if (i < NNODE) {
                    if (adjS[i * NNODE + j] > 0.f) {
                        float e = f1s[i] + f2s[j];
                        v = (e > 0.f) ? e : 0.1f * e;   // LeakyReLU(0.1)
                    } else {
                        v = -1e12f;
                    }
                }
                float mx = warp_max(v);
                float ex = (i < NNODE) ? expf(v - mx) : 0.f;
                float smv = warp_sum(ex);
                if (i < NNODE) att[i * 32 + j] = ex / smv;
            }
        }
        GB();
        for (int idx = lt; idx < NNODE * NC; idx += 128) {
            int i = idx / NC, c = idx % NC;
            float s = 0.f;
            for (int j = 0; j < NNODE; j++) s += att[i * 32 + j] * hX[j * NC + c];
            float r = fmaxf(s, 0.f);
            if (m == 0) fE[i * NC + c] = r; else fM[i * NC + c] = r;
        }
        GB();
    }

    for (int idx = lt; idx < NNODE * 64; idx += 128) {
        int n = idx / 64, o = idx % 64;
        float s = g0b1[o];
#pragma unroll
        for (int k = 0; k < 10; k++) s += fE[n * NC + k] * g0w1[k * 64 + o];
#pragma unroll
        for (int k = 0; k < 10; k++) s += fM[n * NC + k] * g0w1[(10 + k) * 64 + o];
#pragma unroll
        for (int k = 0; k < 10; k++) s += fC[n * NC + k] * g0w1[(20 + k) * 64 + o];
        hg[n * 64 + o] = fmaxf(s, 0.f);
    }
    GB();

#pragma unroll 1
    for (int jj = 0; jj < 8; ++jj) {
        int n = wg + 4 * jj;
        if (n >= NNODE) break;
        float v0 = hg[n * 64 + lane], v1 = hg[n * 64 + lane + 32];
        float l0 = v0 * g0w2[lane * 3 + 0] + v1 * g0w2[(lane + 32) * 3 + 0];
        float l1 = v0 * g0w2[lane * 3 + 1] + v1 * g0w2[(lane + 32) * 3 + 1];
        float l2 = v0 * g0w2[lane * 3 + 2] + v1 * g0w2[(lane + 32) * 3 + 2];
        l0 = warp_sum(l0); l1 = warp_sum(l1); l2 = warp_sum(l2);
        l0 += g0b2[0]; l1 += g0b2[1]; l2 += g0b2[2];
        float mx = fmaxf(l0, fmaxf(l1, l2));
        float e0 = expf(l0 - mx), e1 = expf(l1 - mx), e2 = expf(l2 - mx);
        float inv = 1.f / (e0 + e1 + e2);
        e0 *= inv; e1 *= inv; e2 *= inv;
        if (lane < NC)
            band[n * 40 + g * NC + lane] =
                e0 * fE[n * NC + lane] + e1 * fM[n * NC + lane] + e2 * fC[n * NC + lane];
    }
    __syncthreads();

    // ================= k3 phase (all 512 threads) =======================
    float* hg3  = sm + OFF_HG;
    float* gs4  = sm + OFF_GS;
    float* pool = sm + OFF_POOL;
    float* feat = sm + OFF_FEAT;
    float* h1   = sm + OFF_H1;
    float* p1   = sm + OFF_P1;
    float* h2   = sm + OFF_H2;

    for (int idx = tid; idx < NNODE * 64; idx += 512) {
        int n = idx / 64, o = idx % 64;
        float s = g1b1[o];
#pragma unroll
        for (int k = 0; k < 40; k++) s += band[n * 40 + k] * g1w1[k * 64 + o];
        hg3[n * 64 + o] = fmaxf(s, 0.f);
    }
    __syncthreads();

    {
        int w16 = tid >> 5;
#pragma unroll 1
        for (int jj = 0; jj < 2; ++jj) {
            int n = w16 + 16 * jj;
            if (n >= NNODE) continue;
            float v0 = hg3[n * 64 + lane], v1 = hg3[n * 64 + lane + 32];
            float l[4];
#pragma unroll
            for (int e = 0; e < 4; e++)
                l[e] = v0 * g1w2[lane * 4 + e] + v1 * g1w2[(lane + 32) * 4 + e];
#pragma unroll
            for (int e = 0; e < 4; e++) l[e] = warp_sum(l[e]);
            if (lane == 0) {
#pragma unroll
                for (int e = 0; e < 4; e++) l[e] += g1b2[e];
                float mx = fmaxf(fmaxf(l[0], l[1]), fmaxf(l[2], l[3]));
                float s = 0.f;
#pragma unroll
                for (int e = 0; e < 4; e++) { l[e] = expf(l[e] - mx); s += l[e]; }
                float inv = 1.f / s;
#pragma unroll
                for (int e = 0; e < 4; e++) gs4[n * 4 + e] = l[e] * inv;
            }
        }
    }
    __syncthreads();

    if (tid < 240) {
        int d = tid % 40, ch = tid / 40;
        float s = 0.f;
#pragma unroll
        for (int nn = 0; nn < 5; nn++) {
            int n = ch * 5 + nn;
            s += band[n * 40 + d] * gs4[n * 4 + d / 10];
        }
        pool[ch * 40 + d] = s;
    }
    __syncthreads();
    if (tid < 40) {
        float s = 0.f;
#pragma unroll
        for (int ch = 0; ch < 6; ch++) s += pool[ch * 40 + tid];
        feat[tid] = s * (1.f / 30.f);
    }
    __syncthreads();

    if (tid < 256) {
        int o = tid;
        float s = mlp0b[o];
#pragma unroll
        for (int k = 0; k < 40; k++) s += feat[k] * mlp0w[k * 256 + o];
        h1[o] = fmaxf(s, 0.f);
    }
    __syncthreads();
    if (tid < 256) {
        int o = tid & 31, sl = tid >> 5;
        float s = 0.f;
#pragma unroll
        for (int ki = 0; ki < 32; ki++) {
            int k = sl * 32 + ki;
            s += h1[k] * mlp1w[k * 32 + o];
        }
        p1[sl * 32 + o] = s;
    }
    __syncthreads();
    if (tid < 32) {
        float s = mlp1b[tid];
#pragma unroll
        for (int j = 0; j < 8; j++) s += p1[j * 32 + tid];
        s = fmaxf(s, 0.f);
        h2[tid] = s * (bng[tid] * rsqrtf(1.f + 1e-5f)) + bnb[tid];
    }
    __syncthreads();
    if (tid < 128) {
        int e = tid >> 5;
        float s = h2[lane] * mlp2w[lane * 4 + e];
        s = warp_sum(s);
        if (lane == 0) out[b * 4 + e] = s + mlp2b[e];
    }
}

// =====================================================================
extern "C" void kernel_launch(void* const* d_in, const int* in_sizes, int n_in,
                              void* d_out, int out_size)
{
    const float* eeg       = (const float*)d_in[0];
    const float* wpli_eeg  = (const float*)d_in[1];
    const float* emg       = (const float*)d_in[2];
    const float* wpli_emg  = (const float*)d_in[3];
    const float* cmc       = (const float*)d_in[4];
    const float* cmc_train = (const float*)d_in[5];
    const float* W_eeg     = (const float*)d_in[6];
    const float* a_eeg     = (const float*)d_in[7];
    const float* W_emg     = (const float*)d_in[8];
    const float* a_emg     = (const float*)d_in[9];
    const float* W_cmc     = (const float*)d_in[10];
    const float* b_cmc     = (const float*)d_in[11];
    const float* g0w1      = (const float*)d_in[12];
    const float* g0b1      = (const float*)d_in[13];
    const float* g0w2      = (const float*)d_in[14];
    const float* g0b2      = (const float*)d_in[15];
    const float* g1w1      = (const float*)d_in[16];
    const float* g1b1      = (const float*)d_in[17];
    const float* g1w2      = (const float*)d_in[18];
    const float* g1b2      = (const float*)d_in[19];
    const float* mlp0w     = (const float*)d_in[20];
    const float* mlp0b     = (const float*)d_in[21];
    const float* mlp1w     = (const float*)d_in[22];
    const float* mlp1b     = (const float*)d_in[23];
    const float* mlp2w     = (const float*)d_in[24];
    const float* mlp2b     = (const float*)d_in[25];
    const float* bng       = (const float*)d_in[26];
    const float* bnb       = (const float*)d_in[27];

    const int sm23 = SM23_FLOATS * (int)sizeof(float);   // 103,616 B
    cudaFuncSetAttribute(k23_fused, cudaFuncAttributeMaxDynamicSharedMemorySize,
                         sm23);

    k0_prep<<<604, 256>>>(W_eeg, W_emg, W_cmc, cmc_train);

    k1_gemm<<<2880, 128>>>(eeg, emg, cmc);

    k23_fused<<<NB, 512, sm23>>>(wpli_eeg, wpli_emg, a_eeg, a_emg, b_cmc,
                                 g0w1, g0b1, g0w2, g0b2,
                                 g1w1, g1b1, g1w2, g1b2,
                                 mlp0w, mlp0b, mlp1w, mlp1b, mlp2w, mlp2b,
                                 bng, bnb, (float*)d_out);
}

// round 16
// speedup vs baseline: 1.0256x; 1.0256x over previous
#include <cuda_runtime.h>

// Problem constants
#define NG 4        // bands (G)
#define NB 128      // batch (B)
#define NNODE 30    // nodes (N)
#define NF 5000     // features (F)
#define NC 10       // out channels (C)
#define ROWS_G (NB*NNODE)   // 3840 rows per (mod,g)

// ---------------- device scratch (no allocations allowed) ----------------
__device__ float g_h[3 * NG * ROWS_G * NC];      // h for eeg/emg/cmc
__device__ float g_Wt[12 * NC * NF];             // W transposed: [(mod*4+g)*10+c][k]
__device__ float g_cor[NG * NNODE * NNODE];      // mean over T of cmc_train

typedef unsigned long long ull;

// ---------------- f32x2 packed helpers (sm_103a) ----------------
__device__ __forceinline__ ull pack2(float a, float b) {
    ull r;
    unsigned x = __float_as_uint(a), y = __float_as_uint(b);
    asm("mov.b64 %0, {%1, %2};" : "=l"(r) : "r"(x), "r"(y));
    return r;
}
__device__ __forceinline__ ull dup2(float a) {
    ull r;
    unsigned x = __float_as_uint(a);
    asm("mov.b64 %0, {%1, %1};" : "=l"(r) : "r"(x));
    return r;
}
__device__ __forceinline__ void unpack2(ull v, float& lo, float& hi) {
    unsigned x, y;
    asm("mov.b64 {%0, %1}, %2;" : "=r"(x), "=r"(y) : "l"(v));
    lo = __uint_as_float(x); hi = __uint_as_float(y);
}
__device__ __forceinline__ void ffma2(ull& d, ull a, ull b) {
    asm("fma.rn.f32x2 %0, %1, %2, %0;" : "+l"(d) : "l"(a), "l"(b));
}
__device__ __forceinline__ ull add2(ull a, ull b) {
    ull d;
    asm("add.rn.f32x2 %0, %1, %2;" : "=l"(d) : "l"(a), "l"(b));
    return d;
}
__device__ __forceinline__ float warp_max(float v) {
#pragma unroll
    for (int off = 16; off > 0; off >>= 1)
        v = fmaxf(v, __shfl_xor_sync(0xffffffffu, v, off));
    return v;
}
__device__ __forceinline__ float warp_sum(float v) {
#pragma unroll
    for (int off = 16; off > 0; off >>= 1)
        v += __shfl_xor_sync(0xffffffffu, v, off);
    return v;
}

// =====================================================================
// Kernel 0: prep (R14 version — best measured, 6.8us).
// Blocks 0..479: smem-tiled transpose of a 125-k chunk (12 mg x 40).
// Blocks 480..483: cor = mean_t cmc_train (per g).
// =====================================================================
#define KCH 125

__global__ __launch_bounds__(256) void k0_prep(
    const float* __restrict__ Weeg, const float* __restrict__ Wemg,
    const float* __restrict__ Wcmc, const float* __restrict__ cmc_train)
{
    __shared__ float sbuf[KCH * NC];   // 1250 floats
    int blk = blockIdx.x, tid = threadIdx.x;
    if (blk < 480) {
        int mg = blk / 40, chunk = blk % 40;
        int kbase = chunk * KCH;
        int mod = mg >> 2, g = mg & 3;
        const float* Wsrc = ((mod == 0) ? Weeg : ((mod == 1) ? Wemg : Wcmc))
                            + (size_t)g * NF * NC + (size_t)kbase * NC;
        for (int i = tid; i < KCH * NC; i += 256) sbuf[i] = Wsrc[i];
        __syncthreads();
        for (int t = tid; t < KCH * NC; t += 256) {
            int c = t / KCH, k = t % KCH;
            g_Wt[((size_t)mg * NC + c) * NF + kbase + k] = sbuf[k * NC + c];
        }
    } else {
        int g = blk - 480;
        for (int i = tid; i < NNODE * NNODE; i += 256) {
            float s = 0.f;
#pragma unroll
            for (int t = 0; t < 8; t++)
                s += cmc_train[(size_t)t * (NG * NNODE * NNODE)
                               + (size_t)g * (NNODE * NNODE) + i];
            g_cor[g * NNODE * NNODE + i] = s * 0.125f;
        }
    }
}

// =====================================================================
// Kernel 1: h[mod,g,row,c] = sum_k x[row,k] * W[k,c]
// (R12/R13/R14 passing version; at its empirical DRAM-shape ceiling
// ~4.9TB/s — smem-W, cp.async, burst size, depth, occupancy all
// falsified by controlled experiments in rounds 4-12)
// =====================================================================
#define STEP256(BUF, KB, DOREF, RKB)                                        \
    {                                                                       \
        ull p01_0x = pack2(BUF[0][0].x, BUF[1][0].x);                       \
        ull p01_0y = pack2(BUF[0][0].y, BUF[1][0].y);                       \
        ull p01_0z = pack2(BUF[0][0].z, BUF[1][0].z);                       \
        ull p01_0w = pack2(BUF[0][0].w, BUF[1][0].w);                       \
        ull p23_0x = pack2(BUF[2][0].x, BUF[3][0].x);                       \
        ull p23_0y = pack2(BUF[2][0].y, BUF[3][0].y);                       \
        ull p23_0z = pack2(BUF[2][0].z, BUF[3][0].z);                       \
        ull p23_0w = pack2(BUF[2][0].w, BUF[3][0].w);                       \
        ull p01_1x = pack2(BUF[0][1].x, BUF[1][1].x);                       \
        ull p01_1y = pack2(BUF[0][1].y, BUF[1][1].y);                       \
        ull p01_1z = pack2(BUF[0][1].z, BUF[1][1].z);                       \
        ull p01_1w = pack2(BUF[0][1].w, BUF[1][1].w);                       \
        ull p23_1x = pack2(BUF[2][1].x, BUF[3][1].x);                       \
        ull p23_1y = pack2(BUF[2][1].y, BUF[3][1].y);                       \
        ull p23_1z = pack2(BUF[2][1].z, BUF[3][1].z);                       \
        ull p23_1w = pack2(BUF[2][1].w, BUF[3][1].w);                       \
        if (DOREF) {                                                        \
            _Pragma("unroll")                                               \
            for (int r = 0; r < 4; r++) {                                   \
                BUF[r][0] = __ldcs((const float4*)(p + r * NF + (RKB) + kl));\
                BUF[r][1] = __ldcs((const float4*)(p + r * NF + (RKB) + 128 + kl));\
            }                                                               \
        }                                                                   \
        _Pragma("unroll")                                                   \
        for (int c = 0; c < NC; c++) {                                      \
            float4 w0 = __ldg((const float4*)(wp + (size_t)c * NF + (KB)));  \
            float4 w1 = __ldg((const float4*)(wp + (size_t)c * NF + (KB) + 128));\
            ull wx = dup2(w0.x), wy = dup2(w0.y), wz = dup2(w0.z), ww = dup2(w0.w);\
            ffma2(a01[c], p01_0x, wx); ffma2(a01[c], p01_0y, wy);           \
            ffma2(a01[c], p01_0z, wz); ffma2(a01[c], p01_0w, ww);           \
            ffma2(a23[c], p23_0x, wx); ffma2(a23[c], p23_0y, wy);           \
            ffma2(a23[c], p23_0z, wz); ffma2(a23[c], p23_0w, ww);           \
            wx = dup2(w1.x); wy = dup2(w1.y); wz = dup2(w1.z); ww = dup2(w1.w);\
            ffma2(a01[c], p01_1x, wx); ffma2(a01[c], p01_1y, wy);           \
            ffma2(a01[c], p01_1z, wz); ffma2(a01[c], p01_1w, ww);           \
            ffma2(a23[c], p23_1x, wx); ffma2(a23[c], p23_1y, wy);           \
            ffma2(a23[c], p23_1z, wz); ffma2(a23[c], p23_1w, ww);           \
        }                                                                   \
    }

__global__ __launch_bounds__(128, 3) void k1_gemm(
    const float* __restrict__ eeg, const float* __restrict__ emg,
    const float* __restrict__ cmc)
{
    int blk = blockIdx.x;
    int mod = blk / 960;
    int rem = blk % 960;
    int g   = rem / 240;
    int r0  = (rem % 240) * 16;

    const float* x = (mod == 0) ? eeg : ((mod == 1) ? emg : cmc);

    int tid  = threadIdx.x;
    int lane = tid & 31;
    int wid  = tid >> 5;
    int kl   = lane * 4;

    int r0w = r0 + wid * 4;
    const float* p  = x + ((size_t)g * ROWS_G + r0w) * NF;
    const float* wp = g_Wt + (size_t)(mod * NG + g) * (NC * NF) + kl;

    ull a01[NC], a23[NC];
#pragma unroll
    for (int c = 0; c < NC; c++) { a01[c] = 0ull; a23[c] = 0ull; }

    float4 A[4][2], B[4][2];
#pragma unroll
    for (int r = 0; r < 4; r++) {
        A[r][0] = __ldcs((const float4*)(p + r * NF + 0   + kl));
        A[r][1] = __ldcs((const float4*)(p + r * NF + 128 + kl));
    }
#pragma unroll
    for (int r = 0; r < 4; r++) {
        B[r][0] = __ldcs((const float4*)(p + r * NF + 256 + kl));
        B[r][1] = __ldcs((const float4*)(p + r * NF + 384 + kl));
    }

#pragma unroll 1
    for (int s2 = 0; s2 < 9; ++s2) {
        int kb = s2 * 512;
        STEP256(A, kb, true, kb + 512)
        STEP256(B, kb + 256, (s2 < 8), kb + 768)
    }
    STEP256(A, 4608, false, 0)

    {
        float4 t0 = __ldcs((const float4*)(p + 0 * NF + 4864 + kl));
        float4 t1 = __ldcs((const float4*)(p + 1 * NF + 4864 + kl));
        float4 t2 = __ldcs((const float4*)(p + 2 * NF + 4864 + kl));
        float4 t3 = __ldcs((const float4*)(p + 3 * NF + 4864 + kl));
        ull x01x = pack2(t0.x, t1.x), x01y = pack2(t0.y, t1.y);
        ull x01z = pack2(t0.z, t1.z), x01w = pack2(t0.w, t1.w);
        ull x23x = pack2(t2.x, t3.x), x23y = pack2(t2.y, t3.y);
        ull x23z = pack2(t2.z, t3.z), x23w = pack2(t2.w, t3.w);
#pragma unroll
        for (int c = 0; c < NC; c++) {
            float4 w = __ldg((const float4*)(wp + (size_t)c * NF + 4864));
            ull wx = dup2(w.x), wy = dup2(w.y), wz = dup2(w.z), ww = dup2(w.w);
            ffma2(a01[c], x01x, wx); ffma2(a01[c], x01y, wy);
            ffma2(a01[c], x01z, wz); ffma2(a01[c], x01w, ww);
            ffma2(a23[c], x23x, wx); ffma2(a23[c], x23y, wy);
            ffma2(a23[c], x23z, wz); ffma2(a23[c], x23w, ww);
        }
    }

    if (lane < 2) {
        int ks = 4992 + kl;
        float4 x0 = __ldcs((const float4*)(p + 0 * NF + ks));
        float4 x1 = __ldcs((const float4*)(p + 1 * NF + ks));
        float4 x2 = __ldcs((const float4*)(p + 2 * NF + ks));
        float4 x3 = __ldcs((const float4*)(p + 3 * NF + ks));
        ull x01x = pack2(x0.x, x1.x), x01y = pack2(x0.y, x1.y);
        ull x01z = pack2(x0.z, x1.z), x01w = pack2(x0.w, x1.w);
        ull x23x = pack2(x2.x, x3.x), x23y = pack2(x2.y, x3.y);
        ull x23z = pack2(x2.z, x3.z), x23w = pack2(x2.w, x3.w);
#pragma unroll
        for (int c = 0; c < NC; c++) {
            float4 w = __ldg((const float4*)(wp + (size_t)c * NF + 4992));
            ull wx = dup2(w.x), wy = dup2(w.y), wz = dup2(w.z), ww = dup2(w.w);
            ffma2(a01[c], x01x, wx); ffma2(a01[c], x01y, wy);
            ffma2(a01[c], x01z, wz); ffma2(a01[c], x01w, ww);
            ffma2(a23[c], x23x, wx); ffma2(a23[c], x23y, wy);
            ffma2(a23[c], x23z, wz); ffma2(a23[c], x23w, ww);
        }
    }

    size_t outbase = ((size_t)(mod * NG + g) * ROWS_G + r0w) * NC;
#pragma unroll
    for (int c = 0; c < NC; c++) {
        ull v = a01[c];
#pragma unroll
        for (int off = 16; off > 0; off >>= 1)
            v = add2(v, __shfl_down_sync(0xffffffffu, v, off));
        if (lane == 0) {
            float lo, hi; unpack2(v, lo, hi);
            g_h[outbase + c]      = lo;
            g_h[outbase + NC + c] = hi;
        }
        v = a23[c];
#pragma unroll
        for (int off = 16; off > 0; off >>= 1)
            v = add2(v, __shfl_down_sync(0xffffffffu, v, off));
        if (lane == 0) {
            float lo, hi; unpack2(v, lo, hi);
            g_h[outbase + 2 * NC + c] = lo;
            g_h[outbase + 3 * NC + c] = hi;
        }
    }
}

// =====================================================================
// Kernel 2+3 FUSED: (R13/R14 passing version)
// =====================================================================
#define OFF_HX   0
#define OFF_FE   1200
#define OFF_FM   2400
#define OFF_FC   3600
#define OFF_ATT  4800
#define OFF_COR  8640
#define OFF_ADJ  12240
#define OFF_F1   15840
#define OFF_F2   15960
#define OFF_HG   16080
#define OFF_BAND 23760
#define OFF_GS   24960
#define OFF_POOL 25080
#define OFF_FEAT 25320
#define OFF_H1   25360
#define OFF_P1   25616
#define OFF_H2   25872
#define SM23_FLOATS 25904

#define GB() asm volatile("bar.sync %0, 128;" :: "r"(g + 1) : "memory")

__global__ __launch_bounds__(512, 1) void k23_fused(
    const float* __restrict__ wpli_eeg, const float* __restrict__ wpli_emg,
    const float* __restrict__ a_eeg, const float* __restrict__ a_emg,
    const float* __restrict__ b_cmc,
    const float* __restrict__ g0w1, const float* __restrict__ g0b1,
    const float* __restrict__ g0w2, const float* __restrict__ g0b2,
    const float* __restrict__ g1w1, const float* __restrict__ g1b1,
    const float* __restrict__ g1w2, const float* __restrict__ g1b2,
    const float* __restrict__ mlp0w, const float* __restrict__ mlp0b,
    const float* __restrict__ mlp1w, const float* __restrict__ mlp1b,
    const float* __restrict__ mlp2w, const float* __restrict__ mlp2b,
    const float* __restrict__ bng, const float* __restrict__ bnb,
    float* __restrict__ out)
{
    extern __shared__ float sm[];
    int b    = blockIdx.x;
    int tid  = threadIdx.x;
    int g    = tid >> 7;            // band group 0..3
    int lt   = tid & 127;
    int lane = tid & 31;
    int wg   = lt >> 5;             // warp within group 0..3

    float* hX   = sm + OFF_HX  + g * 300;     // [30][10]
    float* fE   = sm + OFF_FE  + g * 300;
    float* fM   = sm + OFF_FM  + g * 300;
    float* fC   = sm + OFF_FC  + g * 300;
    float* att  = sm + OFF_ATT + g * 960;     // [30][32]
    float* corS = sm + OFF_COR + g * 900;
    float* adjS = sm + OFF_ADJ + g * 900;
    float* f1s  = sm + OFF_F1  + g * 30;
    float* f2s  = sm + OFF_F2  + g * 30;
    float* hg   = sm + OFF_HG  + g * 1920;    // [30][64]
    float* band = sm + OFF_BAND;              // [30][40] shared by all

    // ================= k2 phase (per-group, named barriers) =============
    for (int i = lt; i < NNODE * NNODE; i += 128)
        corS[i] = g_cor[g * NNODE * NNODE + i];
    {
        size_t hb = ((size_t)(2 * NG + g) * ROWS_G + (size_t)b * NNODE) * NC;
        for (int i = lt; i < NNODE * NC; i += 128)
            hX[i] = g_h[hb + i];
    }
    GB();
    for (int idx = lt; idx < NNODE * NC; idx += 128) {
        int i = idx / NC, c = idx % NC;
        float s = 0.f;
        for (int j = 0; j < NNODE; j++) s += corS[i * NNODE + j] * hX[j * NC + c];
        fC[i * NC + c] = s + b_cmc[g * NC + c];
    }
    GB();

    for (int m = 0; m < 2; ++m) {
        const float* a   = ((m == 0) ? a_eeg : a_emg) + g * 2 * NC;
        const float* adj = ((m == 0) ? wpli_eeg : wpli_emg) + g * NNODE * NNODE;
        size_t hb = ((size_t)(m * NG + g) * ROWS_G + (size_t)b * NNODE) * NC;
        for (int i = lt; i < NNODE * NC; i += 128)
            hX[i] = g_h[hb + i];
        for (int i = lt; i < NNODE * NNODE; i += 128)
            adjS[i] = adj[i];
        GB();
        if (lt < NNODE) {
            float s1 = 0.f, s2 = 0.f;
#pragma unroll
            for (int c = 0; c < NC; c++) {
                s1 += hX[lt * NC + c] * a[c];
                s2 += hX[lt * NC + c] * a[NC + c];
            }
            f1s[lt] = s1; f2s[lt] = s2;
        }
        GB();
        {
            int i = lane;
#pragma unroll 1
            for (int jj = 0; jj < 8; ++jj) {
                int j = wg + 4 * jj;
                if (j >= NNODE) break;
                float v = -1e30f;
                if (i < NNODE) {
                    if (adjS[i * NNODE + j] > 0.f) {
                        float e = f1s[i] + f2s[j];
                        v = (e > 0.f) ? e : 0.1f * e;   // LeakyReLU(0.1)
                    } else {
                        v = -1e12f;
                    }
                }
                float mx = warp_max(v);
                float ex = (i < NNODE) ? expf(v - mx) : 0.f;
                float smv = warp_sum(ex);
                if (i < NNODE) att[i * 32 + j] = ex / smv;
            }
        }
        GB();
        for (int idx = lt; idx < NNODE * NC; idx += 128) {
            int i = idx / NC, c = idx % NC;
            float s = 0.f;
            for (int j = 0; j < NNODE; j++) s += att[i * 32 + j] * hX[j * NC + c];
            float r = fmaxf(s, 0.f);
            if (m == 0) fE[i * NC + c] = r; else fM[i * NC + c] = r;
        }
        GB();
    }

    for (int idx = lt; idx < NNODE * 64; idx += 128) {
        int n = idx / 64, o = idx % 64;
        float s = g0b1[o];
#pragma unroll
        for (int k = 0; k < 10; k++) s += fE[n * NC + k] * g0w1[k * 64 + o];
#pragma unroll
        for (int k = 0; k < 10; k++) s += fM[n * NC + k] * g0w1[(10 + k) * 64 + o];
#pragma unroll
        for (int k = 0; k < 10; k++) s += fC[n * NC + k] * g0w1[(20 + k) * 64 + o];
        hg[n * 64 + o] = fmaxf(s, 0.f);
    }
    GB();

#pragma unroll 1
    for (int jj = 0; jj < 8; ++jj) {
        int n = wg + 4 * jj;
        if (n >= NNODE) break;
        float v0 = hg[n * 64 + lane], v1 = hg[n * 64 + lane + 32];
        float l0 = v0 * g0w2[lane * 3 + 0] + v1 * g0w2[(lane + 32) * 3 + 0];
        float l1 = v0 * g0w2[lane * 3 + 1] + v1 * g0w2[(lane + 32) * 3 + 1];
        float l2 = v0 * g0w2[lane * 3 + 2] + v1 * g0w2[(lane + 32) * 3 + 2];
        l0 = warp_sum(l0); l1 = warp_sum(l1); l2 = warp_sum(l2);
        l0 += g0b2[0]; l1 += g0b2[1]; l2 += g0b2[2];
        float mx = fmaxf(l0, fmaxf(l1, l2));
        float e0 = expf(l0 - mx), e1 = expf(l1 - mx), e2 = expf(l2 - mx);
        float inv = 1.f / (e0 + e1 + e2);
        e0 *= inv; e1 *= inv; e2 *= inv;
        if (lane < NC)
            band[n * 40 + g * NC + lane] =
                e0 * fE[n * NC + lane] + e1 * fM[n * NC + lane] + e2 * fC[n * NC + lane];
    }
    __syncthreads();

    // ================= k3 phase (all 512 threads) =======================
    float* hg3  = sm + OFF_HG;
    float* gs4  = sm + OFF_GS;
    float* pool = sm + OFF_POOL;
    float* feat = sm + OFF_FEAT;
    float* h1   = sm + OFF_H1;
    float* p1   = sm + OFF_P1;
    float* h2   = sm + OFF_H2;

    for (int idx = tid; idx < NNODE * 64; idx += 512) {
        int n = idx / 64, o = idx % 64;
        float s = g1b1[o];
#pragma unroll
        for (int k = 0; k < 40; k++) s += band[n * 40 + k] * g1w1[k * 64 + o];
        hg3[n * 64 + o] = fmaxf(s, 0.f);
    }
    __syncthreads();

    {
        int w16 = tid >> 5;
#pragma unroll 1
        for (int jj = 0; jj < 2; ++jj) {
            int n = w16 + 16 * jj;
            if (n >= NNODE) continue;
            float v0 = hg3[n * 64 + lane], v1 = hg3[n * 64 + lane + 32];
            float l[4];
#pragma unroll
            for (int e = 0; e < 4; e++)
                l[e] = v0 * g1w2[lane * 4 + e] + v1 * g1w2[(lane + 32) * 4 + e];
#pragma unroll
            for (int e = 0; e < 4; e++) l[e] = warp_sum(l[e]);
            if (lane == 0) {
#pragma unroll
                for (int e = 0; e < 4; e++) l[e] += g1b2[e];
                float mx = fmaxf(fmaxf(l[0], l[1]), fmaxf(l[2], l[3]));
                float s = 0.f;
#pragma unroll
                for (int e = 0; e < 4; e++) { l[e] = expf(l[e] - mx); s += l[e]; }
                float inv = 1.f / s;
#pragma unroll
                for (int e = 0; e < 4; e++) gs4[n * 4 + e] = l[e] * inv;
            }
        }
    }
    __syncthreads();

    if (tid < 240) {
        int d = tid % 40, ch = tid / 40;
        float s = 0.f;
#pragma unroll
        for (int nn = 0; nn < 5; nn++) {
            int n = ch * 5 + nn;
            s += band[n * 40 + d] * gs4[n * 4 + d / 10];
        }
        pool[ch * 40 + d] = s;
    }
    __syncthreads();
    if (tid < 40) {
        float s = 0.f;
#pragma unroll
        for (int ch = 0; ch < 6; ch++) s += pool[ch * 40 + tid];
        feat[tid] = s * (1.f / 30.f);
    }
    __syncthreads();

    if (tid < 256) {
        int o = tid;
        float s = mlp0b[o];
#pragma unroll
        for (int k = 0; k < 40; k++) s += feat[k] * mlp0w[k * 256 + o];
        h1[o] = fmaxf(s, 0.f);
    }
    __syncthreads();
    if (tid < 256) {
        int o = tid & 31, sl = tid >> 5;
        float s = 0.f;
#pragma unroll
        for (int ki = 0; ki < 32; ki++) {
            int k = sl * 32 + ki;
            s += h1[k] * mlp1w[k * 32 + o];
        }
        p1[sl * 32 + o] = s;
    }
    __syncthreads();
    if (tid < 32) {
        float s = mlp1b[tid];
#pragma unroll
        for (int j = 0; j < 8; j++) s += p1[j * 32 + tid];
        s = fmaxf(s, 0.f);
        h2[tid] = s * (bng[tid] * rsqrtf(1.f + 1e-5f)) + bnb[tid];
    }
    __syncthreads();
    if (tid < 128) {
        int e = tid >> 5;
        float s = h2[lane] * mlp2w[lane * 4 + e];
        s = warp_sum(s);
        if (lane == 0) out[b * 4 + e] = s + mlp2b[e];
    }
}

// =====================================================================
extern "C" void kernel_launch(void* const* d_in, const int* in_sizes, int n_in,
                              void* d_out, int out_size)
{
    const float* eeg       = (const float*)d_in[0];
    const float* wpli_eeg  = (const float*)d_in[1];
    const float* emg       = (const float*)d_in[2];
    const float* wpli_emg  = (const float*)d_in[3];
    const float* cmc       = (const float*)d_in[4];
    const float* cmc_train = (const float*)d_in[5];
    const float* W_eeg     = (const float*)d_in[6];
    const float* a_eeg     = (const float*)d_in[7];
    const float* W_emg     = (const float*)d_in[8];
    const float* a_emg     = (const float*)d_in[9];
    const float* W_cmc     = (const float*)d_in[10];
    const float* b_cmc     = (const float*)d_in[11];
    const float* g0w1      = (const float*)d_in[12];
    const float* g0b1      = (const float*)d_in[13];
    const float* g0w2      = (const float*)d_in[14];
    const float* g0b2      = (const float*)d_in[15];
    const float* g1w1      = (const float*)d_in[16];
    const float* g1b1      = (const float*)d_in[17];
    const float* g1w2      = (const float*)d_in[18];
    const float* g1b2      = (const float*)d_in[19];
    const float* mlp0w     = (const float*)d_in[20];
    const float* mlp0b     = (const float*)d_in[21];
    const float* mlp1w     = (const float*)d_in[22];
    const float* mlp1b     = (const float*)d_in[23];
    const float* mlp2w     = (const float*)d_in[24];
    const float* mlp2b     = (const float*)d_in[25];
    const float* bng       = (const float*)d_in[26];
    const float* bnb       = (const float*)d_in[27];

    const int sm23 = SM23_FLOATS * (int)sizeof(float);   // 103,616 B
    cudaFuncSetAttribute(k23_fused, cudaFuncAttributeMaxDynamicSharedMemorySize,
                         sm23);

    k0_prep<<<484, 256>>>(W_eeg, W_emg, W_cmc, cmc_train);

    k1_gemm<<<2880, 128>>>(eeg, emg, cmc);

    k23_fused<<<NB, 512, sm23>>>(wpli_eeg, wpli_emg, a_eeg, a_emg, b_cmc,
                                 g0w1, g0b1, g0w2, g0b2,
                                 g1w1, g1b1, g1w2, g1b2,
                                 mlp0w, mlp0b, mlp1w, mlp1b, mlp2w, mlp2b,
                                 bng, bnb, (float*)d_out);
}